// round 7
// baseline (speedup 1.0000x reference)
#include <cuda_runtime.h>

#define N_NODES 100000
#define N_EDGES 1000000
#define N_GRAPHS 512

typedef unsigned long long u64;

// Scratch (device globals — no allocation allowed)
__device__ float g_h[N_NODES * 64];     // node features   (25.6 MB)
__device__ float g_agg[N_NODES * 64];   // gather target   (25.6 MB)
__device__ float g_e[N_EDGES * 64];     // edge embeddings, CSR-permuted (256 MB)
__device__ int   g_row[N_NODES + 1];    // CSR row offsets (by dst)
__device__ int   g_cur[N_NODES];        // fill cursors
__device__ int   g_src[N_EDGES];        // src node per CSR slot
__device__ int   g_pos[N_EDGES];        // edge id -> CSR slot

// ---------------- packed f32x2 helpers (sm_100+) ----------------
__device__ __forceinline__ u64 pk2(float x) {
    u64 r; asm("mov.b64 %0, {%1, %1};" : "=l"(r) : "f"(x)); return r;
}
__device__ __forceinline__ u64 pk(float x, float y) {
    u64 r; asm("mov.b64 %0, {%1, %2};" : "=l"(r) : "f"(x), "f"(y)); return r;
}
__device__ __forceinline__ float2 upk(u64 v) {
    float2 f; asm("mov.b64 {%0, %1}, %2;" : "=f"(f.x), "=f"(f.y) : "l"(v)); return f;
}
__device__ __forceinline__ u64 ffma2(u64 a, u64 b, u64 c) {
    u64 d; asm("fma.rn.f32x2 %0, %1, %2, %3;" : "=l"(d) : "l"(a), "l"(b), "l"(c)); return d;
}
__device__ __forceinline__ void red4(float* p, float x, float y, float z, float w) {
    asm volatile("red.global.add.v4.f32 [%0], {%1, %2, %3, %4};"
                 :: "l"(p), "f"(x), "f"(y), "f"(z), "f"(w) : "memory");
}

// ================= quad-cooperative MLP =================
// Thread layout: 4 consecutive lanes (a "quad") share a pair of rows.
// Lane quad-position q owns output columns [q*16, q*16+16) of both rows,
// and holds input chunk [q*(KIN/4), (q+1)*(KIN/4)) of both rows in regs.
// Weights staged in smem with per-quarter skew so the 4 quad addresses
// hit disjoint banks (1 wavefront per LDS.128).

#define W0Q(KIN) ((KIN) * 16 + 4)
#define W1Q      (64 * 16 + 4)

template<int KIN>
__device__ __forceinline__ void stage_weights(
    float* w0s, float* w1s, float* b0s, float* b1s,
    const float* __restrict__ w0, const float* __restrict__ b0,
    const float* __restrict__ w1, const float* __restrict__ b1)
{
    for (int i = threadIdx.x; i < KIN * 64; i += blockDim.x) {
        int k = i >> 6, c = i & 63, q = c >> 4, jf = c & 15;
        w0s[q * W0Q(KIN) + k * 16 + jf] = w0[i];
    }
    for (int i = threadIdx.x; i < 64 * 64; i += blockDim.x) {
        int k = i >> 6, c = i & 63, q = c >> 4, jf = c & 15;
        w1s[q * W1Q + k * 16 + jf] = w1[i];
    }
    for (int i = threadIdx.x; i < 64; i += blockDim.x) { b0s[i] = b0[i]; b1s[i] = b1[i]; }
}

// load this lane's input quarter for one row
template<int KIN>
__device__ __forceinline__ void load_quarter(const float* __restrict__ base,
                                             long long row, int q, float* x) {
    const float4* p = (const float4*)(base + row * KIN + q * (KIN / 4));
    #pragma unroll
    for (int i = 0; i < KIN / 16; i++) {
        float4 t = p[i];
        x[4*i] = t.x; x[4*i+1] = t.y; x[4*i+2] = t.z; x[4*i+3] = t.w;
    }
}

// Layer 1 + ReLU: inputs xa/xb (KIN/4 regs each), outputs ha/hb (8 u64, cols q*16..)
template<int KIN>
__device__ __forceinline__ void mlp_layer1(
    const float* xa, const float* xb, u64* ha, u64* hb,
    const float* w0s, const float* b0s, int q, int quadbase)
{
    const int KQ = KIN / 4;
    const u64* b0v = (const u64*)(b0s + q * 16);
    #pragma unroll
    for (int j = 0; j < 8; j++) { ha[j] = b0v[j]; hb[j] = b0v[j]; }
    const float* w0q = w0s + q * W0Q(KIN);
    #pragma unroll 1
    for (int o = 0; o < 4; o++) {
        #pragma unroll
        for (int i = 0; i < KQ; i++) {
            int k = o * KQ + i;
            float va = __shfl_sync(0xffffffffu, xa[i], quadbase + o);
            float vb = __shfl_sync(0xffffffffu, xb[i], quadbase + o);
            u64 a0 = pk2(va), a1 = pk2(vb);
            const ulonglong2* wr = (const ulonglong2*)(w0q + k * 16);
            #pragma unroll
            for (int j = 0; j < 4; j++) {
                ulonglong2 w = wr[j];
                ha[2*j]   = ffma2(a0, w.x, ha[2*j]);
                ha[2*j+1] = ffma2(a0, w.y, ha[2*j+1]);
                hb[2*j]   = ffma2(a1, w.x, hb[2*j]);
                hb[2*j+1] = ffma2(a1, w.y, hb[2*j+1]);
            }
        }
    }
    #pragma unroll
    for (int j = 0; j < 8; j++) {
        float2 fa = upk(ha[j]); ha[j] = pk(fmaxf(fa.x, 0.f), fmaxf(fa.y, 0.f));
        float2 fb = upk(hb[j]); hb[j] = pk(fmaxf(fb.x, 0.f), fmaxf(fb.y, 0.f));
    }
}

// Layer 2: caller pre-initializes aa/ab (bias, optionally + residual)
__device__ __forceinline__ void mlp_layer2(
    const u64* ha, const u64* hb, u64* aa, u64* ab,
    const float* w1s, int q, int quadbase)
{
    const float* w1q = w1s + q * W1Q;
    #pragma unroll 1
    for (int o = 0; o < 4; o++) {
        #pragma unroll
        for (int i = 0; i < 8; i++) {
            int k2 = o * 8 + i;   // hidden pair (2k2, 2k2+1)
            u64 va = __shfl_sync(0xffffffffu, (unsigned long long)ha[i], quadbase + o);
            u64 vb = __shfl_sync(0xffffffffu, (unsigned long long)hb[i], quadbase + o);
            float2 fa = upk(va), fb = upk(vb);
            u64 a0 = pk2(fa.x), a1 = pk2(fa.y);
            u64 c0 = pk2(fb.x), c1 = pk2(fb.y);
            const ulonglong2* r0 = (const ulonglong2*)(w1q + (2 * k2) * 16);
            const ulonglong2* r1 = (const ulonglong2*)(w1q + (2 * k2 + 1) * 16);
            #pragma unroll
            for (int j = 0; j < 4; j++) {
                ulonglong2 u = r0[j], v = r1[j];
                aa[2*j]   = ffma2(a0, u.x, aa[2*j]);
                aa[2*j+1] = ffma2(a0, u.y, aa[2*j+1]);
                aa[2*j]   = ffma2(a1, v.x, aa[2*j]);
                aa[2*j+1] = ffma2(a1, v.y, aa[2*j+1]);
                ab[2*j]   = ffma2(c0, u.x, ab[2*j]);
                ab[2*j+1] = ffma2(c0, u.y, ab[2*j+1]);
                ab[2*j]   = ffma2(c1, v.x, ab[2*j]);
                ab[2*j+1] = ffma2(c1, v.y, ab[2*j+1]);
            }
        }
    }
}

__device__ __forceinline__ void store16(float* p, const u64* a) {
    float4* v = (float4*)p;
    #pragma unroll
    for (int i = 0; i < 4; i++) {
        float2 x = upk(a[2*i]), y = upk(a[2*i+1]);
        v[i] = make_float4(x.x, x.y, y.x, y.y);
    }
}
__device__ __forceinline__ void store16_relu(float* p, const u64* a) {
    float4* v = (float4*)p;
    #pragma unroll
    for (int i = 0; i < 4; i++) {
        float2 x = upk(a[2*i]), y = upk(a[2*i+1]);
        v[i] = make_float4(fmaxf(x.x, 0.f), fmaxf(x.y, 0.f), fmaxf(y.x, 0.f), fmaxf(y.y, 0.f));
    }
}
__device__ __forceinline__ void store16_cs(float* p, const u64* a) {
    float4* v = (float4*)p;
    #pragma unroll
    for (int i = 0; i < 4; i++) {
        float2 x = upk(a[2*i]), y = upk(a[2*i+1]);
        __stcs(&v[i], make_float4(x.x, x.y, y.x, y.y));
    }
}

// ---------------- CSR construction ----------------
__global__ void k_zero_row() {
    int i = blockIdx.x * 256 + threadIdx.x;
    if (i <= N_NODES) g_row[i] = 0;
}

__global__ void k_count(const int* __restrict__ ei) {
    int e = blockIdx.x * 256 + threadIdx.x;
    if (e < N_EDGES) atomicAdd(&g_row[ei[N_EDGES + e]], 1);
}

__global__ void __launch_bounds__(1024) k_scan() {
    __shared__ int warp_tot[32];
    __shared__ int carry_s, tot_s;
    int tid = threadIdx.x, lane = tid & 31, wid = tid >> 5;
    if (tid == 0) carry_s = 0;
    __syncthreads();
    for (int base = 0; base < N_NODES; base += 4096) {
        int idx = base + tid * 4;
        int v0 = (idx     < N_NODES) ? g_row[idx]     : 0;
        int v1 = (idx + 1 < N_NODES) ? g_row[idx + 1] : 0;
        int v2 = (idx + 2 < N_NODES) ? g_row[idx + 2] : 0;
        int v3 = (idx + 3 < N_NODES) ? g_row[idx + 3] : 0;
        int s0 = v0, s1 = s0 + v1, s2 = s1 + v2, s3 = s2 + v3;
        int tsum = s3;
        int incl = tsum;
        #pragma unroll
        for (int off = 1; off < 32; off <<= 1) {
            int t = __shfl_up_sync(0xffffffff, incl, off);
            if (lane >= off) incl += t;
        }
        if (lane == 31) warp_tot[wid] = incl;
        __syncthreads();
        if (wid == 0) {
            int w = warp_tot[lane];
            int wi = w;
            #pragma unroll
            for (int off = 1; off < 32; off <<= 1) {
                int t = __shfl_up_sync(0xffffffff, wi, off);
                if (lane >= off) wi += t;
            }
            warp_tot[lane] = wi - w;
            if (lane == 31) tot_s = wi;
        }
        __syncthreads();
        int eb = carry_s + warp_tot[wid] + (incl - tsum);
        if (idx     < N_NODES) { g_row[idx]     = eb;      g_cur[idx]     = eb; }
        if (idx + 1 < N_NODES) { g_row[idx + 1] = eb + s0; g_cur[idx + 1] = eb + s0; }
        if (idx + 2 < N_NODES) { g_row[idx + 2] = eb + s1; g_cur[idx + 2] = eb + s1; }
        if (idx + 3 < N_NODES) { g_row[idx + 3] = eb + s2; g_cur[idx + 3] = eb + s2; }
        __syncthreads();
        if (tid == 0) carry_s += tot_s;
        __syncthreads();
    }
    if (tid == 0) g_row[N_NODES] = N_EDGES;
}

__global__ void k_fill(const int* __restrict__ ei) {
    int e = blockIdx.x * 256 + threadIdx.x;
    if (e >= N_EDGES) return;
    int src = ei[e];
    int dst = ei[N_EDGES + e];
    int p = atomicAdd(&g_cur[dst], 1);
    g_src[p] = src;
    g_pos[e] = p;
}

// ---------------- compute kernels ----------------
__global__ void __launch_bounds__(256)
k_node_init(const float* __restrict__ x,
            const float* __restrict__ w0, const float* __restrict__ b0,
            const float* __restrict__ w1, const float* __restrict__ b1) {
    __shared__ __align__(16) float w0s[4 * W0Q(32)], w1s[4 * W1Q], b0s[64], b1s[64];
    stage_weights<32>(w0s, w1s, b0s, b1s, w0, b0, w1, b1);
    __syncthreads();
    int tid = threadIdx.x, q = tid & 3, quadbase = (tid & 31) & ~3;
    int ra = (blockIdx.x * 64 + (tid >> 2)) * 2, rb = ra + 1;
    long long la = min(ra, N_NODES - 1), lb = min(rb, N_NODES - 1);
    float xa[8], xb[8];
    load_quarter<32>(x, la, q, xa);
    load_quarter<32>(x, lb, q, xb);
    u64 ha[8], hb[8], aa[8], ab[8];
    mlp_layer1<32>(xa, xb, ha, hb, w0s, b0s, q, quadbase);
    const u64* b1v = (const u64*)(b1s + q * 16);
    #pragma unroll
    for (int j = 0; j < 8; j++) { aa[j] = b1v[j]; ab[j] = b1v[j]; }
    mlp_layer2(ha, hb, aa, ab, w1s, q, quadbase);
    if (ra < N_NODES) store16(g_h + (size_t)ra * 64 + q * 16, aa);
    if (rb < N_NODES) store16(g_h + (size_t)rb * 64 + q * 16, ab);
}

__global__ void __launch_bounds__(256)
k_edge_init(const float* __restrict__ ea,
            const float* __restrict__ w0, const float* __restrict__ b0,
            const float* __restrict__ w1, const float* __restrict__ b1) {
    __shared__ __align__(16) float w0s[4 * W0Q(16)], w1s[4 * W1Q], b0s[64], b1s[64];
    stage_weights<16>(w0s, w1s, b0s, b1s, w0, b0, w1, b1);
    __syncthreads();
    int tid = threadIdx.x, q = tid & 3, quadbase = (tid & 31) & ~3;
    int ra = (blockIdx.x * 64 + (tid >> 2)) * 2, rb = ra + 1;
    long long la = min(ra, N_EDGES - 1), lb = min(rb, N_EDGES - 1);
    float xa[4], xb[4];
    load_quarter<16>(ea, la, q, xa);
    load_quarter<16>(ea, lb, q, xb);
    u64 ha[8], hb[8], aa[8], ab[8];
    mlp_layer1<16>(xa, xb, ha, hb, w0s, b0s, q, quadbase);
    const u64* b1v = (const u64*)(b1s + q * 16);
    #pragma unroll
    for (int j = 0; j < 8; j++) { aa[j] = b1v[j]; ab[j] = b1v[j]; }
    mlp_layer2(ha, hb, aa, ab, w1s, q, quadbase);
    int pa = __ldg(&g_pos[la]), pb = __ldg(&g_pos[lb]);
    if (ra < N_EDGES) store16_cs(g_e + (size_t)pa * 64 + q * 16, aa);
    if (rb < N_EDGES) store16_cs(g_e + (size_t)pb * 64 + q * 16, ab);
}

__global__ void k_zero_out(float4* out) {
    int i = blockIdx.x * 256 + threadIdx.x;
    out[i] = make_float4(0.f, 0.f, 0.f, 0.f);
}

// Gather (atomic-free, sequential e): 16 lanes per node.
__global__ void __launch_bounds__(256)
k_gather() {
    int gid = blockIdx.x * 256 + threadIdx.x;
    int n = gid >> 4, lane = gid & 15;
    if (n >= N_NODES) return;
    int beg = g_row[n], end = g_row[n + 1];
    float4 acc = make_float4(0.f, 0.f, 0.f, 0.f);
    for (int s = beg; s < end; s++) {
        int src = __ldg(&g_src[s]);
        float4 ev = __ldcs((const float4*)g_e + (size_t)s * 16 + lane);
        float4 hv = __ldg((const float4*)g_h + (size_t)src * 16 + lane);
        acc.x += fmaxf(hv.x + ev.x, 0.f);
        acc.y += fmaxf(hv.y + ev.y, 0.f);
        acc.z += fmaxf(hv.z + ev.z, 0.f);
        acc.w += fmaxf(hv.w + ev.w, 0.f);
    }
    ((float4*)g_agg)[(size_t)n * 16 + lane] = acc;
}

// fused input loader for conv layers: t = agg + 1.1*h (quarter), also returns h pairs
__device__ __forceinline__ void load_conv_quarter(long long row, int q, float* x, u64* hres) {
    const float4* pa = (const float4*)(g_agg + row * 64 + q * 16);
    const float4* ph = (const float4*)(g_h + row * 64 + q * 16);
    #pragma unroll
    for (int i = 0; i < 4; i++) {
        float4 a = pa[i], h = ph[i];
        x[4*i]   = fmaf(1.1f, h.x, a.x);
        x[4*i+1] = fmaf(1.1f, h.y, a.y);
        x[4*i+2] = fmaf(1.1f, h.z, a.z);
        x[4*i+3] = fmaf(1.1f, h.w, a.w);
        hres[2*i]   = pk(h.x, h.y);
        hres[2*i+1] = pk(h.z, h.w);
    }
}

// h = relu(h + mlp2(agg + 1.1*h))   (residual folded into acc init)
__global__ void __launch_bounds__(256)
k_node_update(const float* __restrict__ w0, const float* __restrict__ b0,
              const float* __restrict__ w1, const float* __restrict__ b1) {
    __shared__ __align__(16) float w0s[4 * W0Q(64)], w1s[4 * W1Q], b0s[64], b1s[64];
    stage_weights<64>(w0s, w1s, b0s, b1s, w0, b0, w1, b1);
    __syncthreads();
    int tid = threadIdx.x, q = tid & 3, quadbase = (tid & 31) & ~3;
    int ra = (blockIdx.x * 64 + (tid >> 2)) * 2, rb = ra + 1;
    long long la = min(ra, N_NODES - 1), lb = min(rb, N_NODES - 1);
    float xa[16], xb[16];
    u64 aa[8], ab[8];
    load_conv_quarter(la, q, xa, aa);   // aa = h pairs (residual)
    load_conv_quarter(lb, q, xb, ab);
    const u64* b1v = (const u64*)(b1s + q * 16);
    #pragma unroll
    for (int j = 0; j < 8; j++) {       // acc = bias + residual
        float2 r = upk(aa[j]), b = upk(b1v[j]);
        aa[j] = pk(r.x + b.x, r.y + b.y);
        r = upk(ab[j]);
        ab[j] = pk(r.x + b.x, r.y + b.y);
    }
    u64 ha[8], hb[8];
    mlp_layer1<64>(xa, xb, ha, hb, w0s, b0s, q, quadbase);
    mlp_layer2(ha, hb, aa, ab, w1s, q, quadbase);
    if (ra < N_NODES) store16_relu(g_h + (size_t)ra * 64 + q * 16, aa);
    if (rb < N_NODES) store16_relu(g_h + (size_t)rb * 64 + q * 16, ab);
}

// final conv: mlp2(agg + 1.1*h), pool via red.v4 into d_out[batch[n]]
__global__ void __launch_bounds__(256)
k_node_final(const int* __restrict__ batch,
             const float* __restrict__ w0, const float* __restrict__ b0,
             const float* __restrict__ w1, const float* __restrict__ b1,
             float* __restrict__ out) {
    __shared__ __align__(16) float w0s[4 * W0Q(64)], w1s[4 * W1Q], b0s[64], b1s[64];
    stage_weights<64>(w0s, w1s, b0s, b1s, w0, b0, w1, b1);
    __syncthreads();
    int tid = threadIdx.x, q = tid & 3, quadbase = (tid & 31) & ~3;
    int ra = (blockIdx.x * 64 + (tid >> 2)) * 2, rb = ra + 1;
    long long la = min(ra, N_NODES - 1), lb = min(rb, N_NODES - 1);
    float xa[16], xb[16];
    u64 dump[8];
    load_conv_quarter(la, q, xa, dump);
    load_conv_quarter(lb, q, xb, dump);
    u64 ha[8], hb[8], aa[8], ab[8];
    mlp_layer1<64>(xa, xb, ha, hb, w0s, b0s, q, quadbase);
    const u64* b1v = (const u64*)(b1s + q * 16);
    #pragma unroll
    for (int j = 0; j < 8; j++) { aa[j] = b1v[j]; ab[j] = b1v[j]; }
    mlp_layer2(ha, hb, aa, ab, w1s, q, quadbase);
    int ba = __ldg(&batch[la]), bb = __ldg(&batch[lb]);
    if (ra < N_NODES) {
        float* p = out + (size_t)ba * 64 + q * 16;
        #pragma unroll
        for (int i = 0; i < 4; i++) {
            float2 x = upk(aa[2*i]), y = upk(aa[2*i+1]);
            red4(p + i * 4, x.x, x.y, y.x, y.y);
        }
    }
    if (rb < N_NODES) {
        float* p = out + (size_t)bb * 64 + q * 16;
        #pragma unroll
        for (int i = 0; i < 4; i++) {
            float2 x = upk(ab[2*i]), y = upk(ab[2*i+1]);
            red4(p + i * 4, x.x, x.y, y.x, y.y);
        }
    }
}

extern "C" void kernel_launch(void* const* d_in, const int* in_sizes, int n_in,
                              void* d_out, int out_size) {
    const float* x   = (const float*)d_in[0];
    const int*   ei  = (const int*)d_in[1];
    const float* ea  = (const float*)d_in[2];
    const int*   bat = (const int*)d_in[3];
    const float* wn0 = (const float*)d_in[4],  *bn0 = (const float*)d_in[5];
    const float* wn1 = (const float*)d_in[6],  *bn1 = (const float*)d_in[7];
    const float* we0 = (const float*)d_in[8],  *be0 = (const float*)d_in[9];
    const float* we1 = (const float*)d_in[10], *be1 = (const float*)d_in[11];
    const float* cw0 = (const float*)d_in[12], *cb0 = (const float*)d_in[13];
    const float* cw1 = (const float*)d_in[14], *cb1 = (const float*)d_in[15];
    const float* lw0 = (const float*)d_in[16], *lb0 = (const float*)d_in[17];
    const float* lw1 = (const float*)d_in[18], *lb1 = (const float*)d_in[19];
    float* out = (float*)d_out;

    const int E256        = (N_EDGES + 255) / 256;
    const int NODE_BLOCKS = (N_NODES + 127) / 128;   // 128 rows per block
    const int EDGE_BLOCKS = (N_EDGES + 127) / 128;
    const int GATH_BLOCKS = (N_NODES * 16 + 255) / 256;

    // launch index 3 = k_node_init (the slot ncu captures)
    k_zero_row<<<(N_NODES + 1 + 255) / 256, 256>>>();            // 0
    k_count<<<E256, 256>>>(ei);                                   // 1
    k_scan<<<1, 1024>>>();                                        // 2
    k_node_init<<<NODE_BLOCKS, 256>>>(x, wn0, bn0, wn1, bn1);     // 3  <- profiled
    k_fill<<<E256, 256>>>(ei);                                    // 4
    k_edge_init<<<EDGE_BLOCKS, 256>>>(ea, we0, be0, we1, be1);    // 5
    k_zero_out<<<(N_GRAPHS * 64 / 4) / 256, 256>>>((float4*)out); // 6

    for (int l = 0; l < 3; l++) {
        k_gather<<<GATH_BLOCKS, 256>>>();
        k_node_update<<<NODE_BLOCKS, 256>>>(cw0 + l * 64 * 64, cb0 + l * 64,
                                            cw1 + l * 64 * 64, cb1 + l * 64);
    }
    k_gather<<<GATH_BLOCKS, 256>>>();
    k_node_final<<<NODE_BLOCKS, 256>>>(bat, lw0, lb0, lw1, lb1, out);
}

// round 8
// speedup vs baseline: 1.0722x; 1.0722x over previous
#include <cuda_runtime.h>

#define N_NODES 100000
#define N_EDGES 1000000
#define N_GRAPHS 512

#define TILE  256           // rows per block
#define PITCH 260           // transposed-tile row pitch (floats), 16B-aligned

typedef unsigned long long u64;

// Scratch (device globals — no allocation allowed)
__device__ float g_h[N_NODES * 64];     // node features   (25.6 MB)
__device__ float g_agg[N_NODES * 64];   // gather target   (25.6 MB)
__device__ float g_e[N_EDGES * 64];     // edge embeddings, CSR-permuted (256 MB)
__device__ int   g_row[N_NODES + 1];    // CSR row offsets (by dst)
__device__ int   g_cur[N_NODES];        // fill cursors
__device__ int   g_src[N_EDGES];        // src node per CSR slot
__device__ int   g_pos[N_EDGES];        // edge id -> CSR slot

// ---------------- packed f32x2 helpers (sm_100+) ----------------
__device__ __forceinline__ u64 pk2(float x) {
    u64 r; asm("mov.b64 %0, {%1, %1};" : "=l"(r) : "f"(x)); return r;
}
__device__ __forceinline__ u64 pk(float x, float y) {
    u64 r; asm("mov.b64 %0, {%1, %2};" : "=l"(r) : "f"(x), "f"(y)); return r;
}
__device__ __forceinline__ float2 upk(u64 v) {
    float2 f; asm("mov.b64 {%0, %1}, %2;" : "=f"(f.x), "=f"(f.y) : "l"(v)); return f;
}
__device__ __forceinline__ u64 ffma2(u64 a, u64 b, u64 c) {
    u64 d; asm("fma.rn.f32x2 %0, %1, %2, %3;" : "=l"(d) : "l"(a), "l"(b), "l"(c)); return d;
}
__device__ __forceinline__ void red4(float* p, float x, float y, float z, float w) {
    asm volatile("red.global.add.v4.f32 [%0], {%1, %2, %3, %4};"
                 :: "l"(p), "f"(x), "f"(y), "f"(z), "f"(w) : "memory");
}

// ================= SGEMM-style MLP tile core =================
// Block: 256 threads, tile TILE(=256) rows x 64 cols.
// Thread (tr = tid>>3 in [0,32), tc = tid&7 in [0,8)) owns rows tr*8..+8,
// cols tc*8..+8 (held as 8x4 u64 f32x2 pairs).
// Inputs live TRANSPOSED in smem: sT[k][row], pitch PITCH.
// Weights row-major in smem: sW[k][64].

// acc[r*4+j] += A[row r][k] * W[k][cols]
template<int K>
__device__ __forceinline__ void layer_tile(const float* sT, const float* sW,
                                           u64* acc, int tr, int tc) {
    #pragma unroll 2
    for (int k = 0; k < K; k++) {
        const float4* aP = (const float4*)(sT + k * PITCH + tr * 8);
        float4 a0 = aP[0], a1 = aP[1];
        const ulonglong2* wP = (const ulonglong2*)(sW + k * 64 + tc * 8);
        ulonglong2 wA = wP[0], wB = wP[1];
        u64 w[4] = { wA.x, wA.y, wB.x, wB.y };
        float ar[8] = { a0.x, a0.y, a0.z, a0.w, a1.x, a1.y, a1.z, a1.w };
        #pragma unroll
        for (int r = 0; r < 8; r++) {
            u64 av = pk2(ar[r]);
            #pragma unroll
            for (int j = 0; j < 4; j++) acc[r * 4 + j] = ffma2(av, w[j], acc[r * 4 + j]);
        }
    }
}

__device__ __forceinline__ void init_bias(u64* acc, const float* sB, int tc) {
    const u64* b = (const u64*)sB;
    u64 bv[4];
    #pragma unroll
    for (int j = 0; j < 4; j++) bv[j] = b[tc * 4 + j];
    #pragma unroll
    for (int r = 0; r < 8; r++)
        #pragma unroll
        for (int j = 0; j < 4; j++) acc[r * 4 + j] = bv[j];
}

__device__ __forceinline__ void relu32(u64* h) {
    #pragma unroll
    for (int i = 0; i < 32; i++) {
        float2 f = upk(h[i]);
        h[i] = pk(fmaxf(f.x, 0.f), fmaxf(f.y, 0.f));
    }
}

// store thread's 8x8 block transposed into sT[col][row]
__device__ __forceinline__ void store_T(const u64* h, float* sT, int tr, int tc) {
    #pragma unroll
    for (int c = 0; c < 8; c++) {
        int gc = tc * 8 + c, j = c >> 1;
        float col[8];
        #pragma unroll
        for (int r = 0; r < 8; r++) {
            float2 f = upk(h[r * 4 + j]);
            col[r] = (c & 1) ? f.y : f.x;
        }
        float4* d = (float4*)(sT + gc * PITCH + tr * 8);
        d[0] = make_float4(col[0], col[1], col[2], col[3]);
        d[1] = make_float4(col[4], col[5], col[6], col[7]);
    }
}

__device__ __forceinline__ void stage_copy(float* dst, const float* __restrict__ src, int n) {
    for (int i = threadIdx.x; i < n; i += 256) dst[i] = src[i];
}

// ---------------- CSR construction ----------------
__global__ void k_zero_row() {
    int i = blockIdx.x * 256 + threadIdx.x;
    if (i <= N_NODES) g_row[i] = 0;
}

__global__ void k_count(const int* __restrict__ ei) {
    int e = blockIdx.x * 256 + threadIdx.x;
    if (e < N_EDGES) atomicAdd(&g_row[ei[N_EDGES + e]], 1);
}

__global__ void __launch_bounds__(1024) k_scan() {
    __shared__ int warp_tot[32];
    __shared__ int carry_s, tot_s;
    int tid = threadIdx.x, lane = tid & 31, wid = tid >> 5;
    if (tid == 0) carry_s = 0;
    __syncthreads();
    for (int base = 0; base < N_NODES; base += 4096) {
        int idx = base + tid * 4;
        int v0 = (idx     < N_NODES) ? g_row[idx]     : 0;
        int v1 = (idx + 1 < N_NODES) ? g_row[idx + 1] : 0;
        int v2 = (idx + 2 < N_NODES) ? g_row[idx + 2] : 0;
        int v3 = (idx + 3 < N_NODES) ? g_row[idx + 3] : 0;
        int s0 = v0, s1 = s0 + v1, s2 = s1 + v2, s3 = s2 + v3;
        int tsum = s3;
        int incl = tsum;
        #pragma unroll
        for (int off = 1; off < 32; off <<= 1) {
            int t = __shfl_up_sync(0xffffffff, incl, off);
            if (lane >= off) incl += t;
        }
        if (lane == 31) warp_tot[wid] = incl;
        __syncthreads();
        if (wid == 0) {
            int w = warp_tot[lane];
            int wi = w;
            #pragma unroll
            for (int off = 1; off < 32; off <<= 1) {
                int t = __shfl_up_sync(0xffffffff, wi, off);
                if (lane >= off) wi += t;
            }
            warp_tot[lane] = wi - w;
            if (lane == 31) tot_s = wi;
        }
        __syncthreads();
        int eb = carry_s + warp_tot[wid] + (incl - tsum);
        if (idx     < N_NODES) { g_row[idx]     = eb;      g_cur[idx]     = eb; }
        if (idx + 1 < N_NODES) { g_row[idx + 1] = eb + s0; g_cur[idx + 1] = eb + s0; }
        if (idx + 2 < N_NODES) { g_row[idx + 2] = eb + s1; g_cur[idx + 2] = eb + s1; }
        if (idx + 3 < N_NODES) { g_row[idx + 3] = eb + s2; g_cur[idx + 3] = eb + s2; }
        __syncthreads();
        if (tid == 0) carry_s += tot_s;
        __syncthreads();
    }
    if (tid == 0) g_row[N_NODES] = N_EDGES;
}

__global__ void k_fill(const int* __restrict__ ei) {
    int e = blockIdx.x * 256 + threadIdx.x;
    if (e >= N_EDGES) return;
    int src = ei[e];
    int dst = ei[N_EDGES + e];
    int p = atomicAdd(&g_cur[dst], 1);
    g_src[p] = src;
    g_pos[e] = p;
}

// ---------------- MLP kernels ----------------
// smem layout: [sT 64*PITCH | sW0 KIN*64 | sW1 64*64 | b0 64 | b1 64]

__global__ void __launch_bounds__(256, 2)
k_node_init(const float* __restrict__ x,
            const float* __restrict__ w0, const float* __restrict__ b0,
            const float* __restrict__ w1, const float* __restrict__ b1) {
    extern __shared__ float smem[];
    float* sT  = smem;
    float* sW0 = sT + 64 * PITCH;
    float* sW1 = sW0 + 32 * 64;
    float* sB0 = sW1 + 64 * 64;
    float* sB1 = sB0 + 64;
    stage_copy(sW0, w0, 32 * 64); stage_copy(sW1, w1, 64 * 64);
    stage_copy(sB0, b0, 64);      stage_copy(sB1, b1, 64);
    int tid = threadIdx.x, tc = tid & 7, tr = tid >> 3;
    long long base = (long long)blockIdx.x * TILE;
    // stage input transposed: KIN=32 -> 8 float4 per row
    for (int i = tid; i < TILE * 8; i += 256) {
        int row = i >> 3, k4 = i & 7;
        long long gr = base + row; if (gr >= N_NODES) gr = N_NODES - 1;
        float4 v = ((const float4*)(x + gr * 32))[k4];
        int k = k4 * 4;
        sT[(k + 0) * PITCH + row] = v.x;
        sT[(k + 1) * PITCH + row] = v.y;
        sT[(k + 2) * PITCH + row] = v.z;
        sT[(k + 3) * PITCH + row] = v.w;
    }
    __syncthreads();
    u64 h[32];
    init_bias(h, sB0, tc);
    layer_tile<32>(sT, sW0, h, tr, tc);
    relu32(h);
    __syncthreads();
    store_T(h, sT, tr, tc);
    __syncthreads();
    u64 acc[32];
    init_bias(acc, sB1, tc);
    layer_tile<64>(sT, sW1, acc, tr, tc);
    #pragma unroll
    for (int r = 0; r < 8; r++) {
        long long row = base + tr * 8 + r;
        if (row < N_NODES) {
            float2 a = upk(acc[r*4]), b = upk(acc[r*4+1]), c = upk(acc[r*4+2]), d = upk(acc[r*4+3]);
            float4* o = (float4*)(g_h + row * 64 + tc * 8);
            o[0] = make_float4(a.x, a.y, b.x, b.y);
            o[1] = make_float4(c.x, c.y, d.x, d.y);
        }
    }
}

__global__ void __launch_bounds__(256, 2)
k_edge_init(const float* __restrict__ ea,
            const float* __restrict__ w0, const float* __restrict__ b0,
            const float* __restrict__ w1, const float* __restrict__ b1) {
    extern __shared__ float smem[];
    float* sT  = smem;
    float* sW0 = sT + 64 * PITCH;
    float* sW1 = sW0 + 16 * 64;
    float* sB0 = sW1 + 64 * 64;
    float* sB1 = sB0 + 64;
    stage_copy(sW0, w0, 16 * 64); stage_copy(sW1, w1, 64 * 64);
    stage_copy(sB0, b0, 64);      stage_copy(sB1, b1, 64);
    int tid = threadIdx.x, tc = tid & 7, tr = tid >> 3;
    long long base = (long long)blockIdx.x * TILE;
    for (int i = tid; i < TILE * 4; i += 256) {
        int row = i >> 2, k4 = i & 3;
        long long gr = base + row; if (gr >= N_EDGES) gr = N_EDGES - 1;
        float4 v = ((const float4*)(ea + gr * 16))[k4];
        int k = k4 * 4;
        sT[(k + 0) * PITCH + row] = v.x;
        sT[(k + 1) * PITCH + row] = v.y;
        sT[(k + 2) * PITCH + row] = v.z;
        sT[(k + 3) * PITCH + row] = v.w;
    }
    __syncthreads();
    u64 h[32];
    init_bias(h, sB0, tc);
    layer_tile<16>(sT, sW0, h, tr, tc);
    relu32(h);
    __syncthreads();
    store_T(h, sT, tr, tc);
    __syncthreads();
    u64 acc[32];
    init_bias(acc, sB1, tc);
    layer_tile<64>(sT, sW1, acc, tr, tc);
    #pragma unroll
    for (int r = 0; r < 8; r++) {
        long long row = base + tr * 8 + r;
        if (row < N_EDGES) {
            int p = __ldg(&g_pos[row]);
            float2 a = upk(acc[r*4]), b = upk(acc[r*4+1]), c = upk(acc[r*4+2]), d = upk(acc[r*4+3]);
            float4* o = (float4*)(g_e + (size_t)p * 64 + tc * 8);
            __stcs(&o[0], make_float4(a.x, a.y, b.x, b.y));
            __stcs(&o[1], make_float4(c.x, c.y, d.x, d.y));
        }
    }
}

// conv staging: t = agg + 1.1*h, transposed
__device__ __forceinline__ void stage_conv(float* sT, long long base, long long limit) {
    for (int i = threadIdx.x; i < TILE * 16; i += 256) {
        int row = i >> 4, k4 = i & 15;
        long long gr = base + row; if (gr >= limit) gr = limit - 1;
        float4 a = ((const float4*)(g_agg + gr * 64))[k4];
        float4 h = ((const float4*)(g_h   + gr * 64))[k4];
        int k = k4 * 4;
        sT[(k + 0) * PITCH + row] = fmaf(1.1f, h.x, a.x);
        sT[(k + 1) * PITCH + row] = fmaf(1.1f, h.y, a.y);
        sT[(k + 2) * PITCH + row] = fmaf(1.1f, h.z, a.z);
        sT[(k + 3) * PITCH + row] = fmaf(1.1f, h.w, a.w);
    }
}

__global__ void __launch_bounds__(256, 2)
k_node_update(const float* __restrict__ w0, const float* __restrict__ b0,
              const float* __restrict__ w1, const float* __restrict__ b1) {
    extern __shared__ float smem[];
    float* sT  = smem;
    float* sW0 = sT + 64 * PITCH;
    float* sW1 = sW0 + 64 * 64;
    float* sB0 = sW1 + 64 * 64;
    float* sB1 = sB0 + 64;
    stage_copy(sW0, w0, 64 * 64); stage_copy(sW1, w1, 64 * 64);
    stage_copy(sB0, b0, 64);      stage_copy(sB1, b1, 64);
    int tid = threadIdx.x, tc = tid & 7, tr = tid >> 3;
    long long base = (long long)blockIdx.x * TILE;
    stage_conv(sT, base, N_NODES);
    __syncthreads();
    u64 h[32];
    init_bias(h, sB0, tc);
    layer_tile<64>(sT, sW0, h, tr, tc);
    relu32(h);
    __syncthreads();
    store_T(h, sT, tr, tc);
    __syncthreads();
    u64 acc[32];
    init_bias(acc, sB1, tc);
    layer_tile<64>(sT, sW1, acc, tr, tc);
    // h_new = relu(h_old + mlp_out)
    #pragma unroll
    for (int r = 0; r < 8; r++) {
        long long row = base + tr * 8 + r;
        if (row < N_NODES) {
            float4* o = (float4*)(g_h + row * 64 + tc * 8);
            float4 h0 = o[0], h1 = o[1];
            float2 a = upk(acc[r*4]), b = upk(acc[r*4+1]), c = upk(acc[r*4+2]), d = upk(acc[r*4+3]);
            o[0] = make_float4(fmaxf(h0.x + a.x, 0.f), fmaxf(h0.y + a.y, 0.f),
                               fmaxf(h0.z + b.x, 0.f), fmaxf(h0.w + b.y, 0.f));
            o[1] = make_float4(fmaxf(h1.x + c.x, 0.f), fmaxf(h1.y + c.y, 0.f),
                               fmaxf(h1.z + d.x, 0.f), fmaxf(h1.w + d.y, 0.f));
        }
    }
}

__global__ void __launch_bounds__(256, 2)
k_node_final(const int* __restrict__ batch,
             const float* __restrict__ w0, const float* __restrict__ b0,
             const float* __restrict__ w1, const float* __restrict__ b1,
             float* __restrict__ out) {
    extern __shared__ float smem[];
    float* sT  = smem;
    float* sW0 = sT + 64 * PITCH;
    float* sW1 = sW0 + 64 * 64;
    float* sB0 = sW1 + 64 * 64;
    float* sB1 = sB0 + 64;
    stage_copy(sW0, w0, 64 * 64); stage_copy(sW1, w1, 64 * 64);
    stage_copy(sB0, b0, 64);      stage_copy(sB1, b1, 64);
    int tid = threadIdx.x, tc = tid & 7, tr = tid >> 3;
    long long base = (long long)blockIdx.x * TILE;
    stage_conv(sT, base, N_NODES);
    __syncthreads();
    u64 h[32];
    init_bias(h, sB0, tc);
    layer_tile<64>(sT, sW0, h, tr, tc);
    relu32(h);
    __syncthreads();
    store_T(h, sT, tr, tc);
    __syncthreads();
    u64 acc[32];
    init_bias(acc, sB1, tc);
    layer_tile<64>(sT, sW1, acc, tr, tc);
    #pragma unroll
    for (int r = 0; r < 8; r++) {
        long long row = base + tr * 8 + r;
        if (row < N_NODES) {
            int bg = __ldg(&batch[row]);
            float* p = out + (size_t)bg * 64 + tc * 8;
            float2 a = upk(acc[r*4]), b = upk(acc[r*4+1]), c = upk(acc[r*4+2]), d = upk(acc[r*4+3]);
            red4(p,     a.x, a.y, b.x, b.y);
            red4(p + 4, c.x, c.y, d.x, d.y);
        }
    }
}

__global__ void k_zero_out(float4* out) {
    int i = blockIdx.x * 256 + threadIdx.x;
    out[i] = make_float4(0.f, 0.f, 0.f, 0.f);
}

// Gather (atomic-free, sequential e): 16 lanes per node.
__global__ void __launch_bounds__(256)
k_gather() {
    int gid = blockIdx.x * 256 + threadIdx.x;
    int n = gid >> 4, lane = gid & 15;
    if (n >= N_NODES) return;
    int beg = g_row[n], end = g_row[n + 1];
    float4 acc = make_float4(0.f, 0.f, 0.f, 0.f);
    for (int s = beg; s < end; s++) {
        int src = __ldg(&g_src[s]);
        float4 ev = __ldcs((const float4*)g_e + (size_t)s * 16 + lane);
        float4 hv = __ldg((const float4*)g_h + (size_t)src * 16 + lane);
        acc.x += fmaxf(hv.x + ev.x, 0.f);
        acc.y += fmaxf(hv.y + ev.y, 0.f);
        acc.z += fmaxf(hv.z + ev.z, 0.f);
        acc.w += fmaxf(hv.w + ev.w, 0.f);
    }
    ((float4*)g_agg)[(size_t)n * 16 + lane] = acc;
}

extern "C" void kernel_launch(void* const* d_in, const int* in_sizes, int n_in,
                              void* d_out, int out_size) {
    const float* x   = (const float*)d_in[0];
    const int*   ei  = (const int*)d_in[1];
    const float* ea  = (const float*)d_in[2];
    const int*   bat = (const int*)d_in[3];
    const float* wn0 = (const float*)d_in[4],  *bn0 = (const float*)d_in[5];
    const float* wn1 = (const float*)d_in[6],  *bn1 = (const float*)d_in[7];
    const float* we0 = (const float*)d_in[8],  *be0 = (const float*)d_in[9];
    const float* we1 = (const float*)d_in[10], *be1 = (const float*)d_in[11];
    const float* cw0 = (const float*)d_in[12], *cb0 = (const float*)d_in[13];
    const float* cw1 = (const float*)d_in[14], *cb1 = (const float*)d_in[15];
    const float* lw0 = (const float*)d_in[16], *lb0 = (const float*)d_in[17];
    const float* lw1 = (const float*)d_in[18], *lb1 = (const float*)d_in[19];
    float* out = (float*)d_out;

    const int SM_NODE = (64 * PITCH + 32 * 64 + 64 * 64 + 128) * 4;
    const int SM_EDGE = (64 * PITCH + 16 * 64 + 64 * 64 + 128) * 4;
    const int SM_CONV = (64 * PITCH + 64 * 64 + 64 * 64 + 128) * 4;
    cudaFuncSetAttribute(k_node_init,   cudaFuncAttributeMaxDynamicSharedMemorySize, SM_NODE);
    cudaFuncSetAttribute(k_edge_init,   cudaFuncAttributeMaxDynamicSharedMemorySize, SM_EDGE);
    cudaFuncSetAttribute(k_node_update, cudaFuncAttributeMaxDynamicSharedMemorySize, SM_CONV);
    cudaFuncSetAttribute(k_node_final,  cudaFuncAttributeMaxDynamicSharedMemorySize, SM_CONV);

    const int E256       = (N_EDGES + 255) / 256;
    const int NODE_TILES = (N_NODES + TILE - 1) / TILE;   // 391
    const int EDGE_TILES = (N_EDGES + TILE - 1) / TILE;   // 3907
    const int GATH_BLOCKS = (N_NODES * 16 + 255) / 256;

    // launch index 3 = k_node_init (the slot ncu captures)
    k_zero_row<<<(N_NODES + 1 + 255) / 256, 256>>>();                       // 0
    k_count<<<E256, 256>>>(ei);                                              // 1
    k_scan<<<1, 1024>>>();                                                   // 2
    k_node_init<<<NODE_TILES, 256, SM_NODE>>>(x, wn0, bn0, wn1, bn1);        // 3 <- profiled
    k_fill<<<E256, 256>>>(ei);                                               // 4
    k_edge_init<<<EDGE_TILES, 256, SM_EDGE>>>(ea, we0, be0, we1, be1);       // 5
    k_zero_out<<<(N_GRAPHS * 64 / 4) / 256, 256>>>((float4*)out);            // 6

    for (int l = 0; l < 3; l++) {
        k_gather<<<GATH_BLOCKS, 256>>>();
        k_node_update<<<NODE_TILES, 256, SM_CONV>>>(cw0 + l * 64 * 64, cb0 + l * 64,
                                                    cw1 + l * 64 * 64, cb1 + l * 64);
    }
    k_gather<<<GATH_BLOCKS, 256>>>();
    k_node_final<<<NODE_TILES, 256, SM_CONV>>>(bat, lw0, lb0, lw1, lb1, out);
}